// round 7
// baseline (speedup 1.0000x reference)
#include <cuda_runtime.h>
#include <cuda_bf16.h>

// NeuralODE R7: packed (f32x2) sigmoid fixup for the 4-way shared reciprocal,
// cutting fma-pipe cycles/group 42 -> 30 so MUFU (4 ex2 + 1 rcp per 4 tanh)
// becomes the single binding pipe. Small hot loop (unroll 2, one rk_step/iter)
// keeps SASS L0-resident.

#define NB    131072
#define NSEQ  150
#define ND    2
#define NH    64
#define NPRED 150
#define NSTEPS (NPRED - 1)

typedef unsigned long long u64;

__device__ __forceinline__ u64 pk(float a, float b) {
    u64 r; asm("mov.b64 %0, {%1, %2};" : "=l"(r) : "f"(a), "f"(b)); return r;
}
__device__ __forceinline__ float2 upk(u64 v) {
    float2 r; asm("mov.b64 {%0, %1}, %2;" : "=f"(r.x), "=f"(r.y) : "l"(v)); return r;
}
__device__ __forceinline__ u64 fma2(u64 a, u64 b, u64 c) {
    u64 d; asm("fma.rn.f32x2 %0, %1, %2, %3;" : "=l"(d) : "l"(a), "l"(b), "l"(c)); return d;
}
__device__ __forceinline__ u64 add2(u64 a, u64 b) {
    u64 d; asm("add.rn.f32x2 %0, %1, %2;" : "=l"(d) : "l"(a), "l"(b)); return d;
}
__device__ __forceinline__ u64 mul2(u64 a, u64 b) {
    u64 d; asm("mul.rn.f32x2 %0, %1, %2;" : "=l"(d) : "l"(a), "l"(b)); return d;
}
__device__ __forceinline__ float ex2f(float p) {
    float t; asm("ex2.approx.f32 %0, %1;" : "=f"(t) : "f"(p)); return t;
}
__device__ __forceinline__ float rcpf(float p) {
    float t; asm("rcp.approx.f32 %0, %1;" : "=f"(t) : "f"(p)); return t;
}

// Shared layout per jp (hidden pair {2jp, 2jp+1}):
//   sW[jp] = ulonglong2 { {s*wx_j, s*wx_j1}, {s*wy_j, s*wy_j1} }
//   sV[jp] = ulonglong2 { {vx_j, vx_j1},   {vy_j, vy_j1} }
//   sB[jp] = u64 {s*b_j, s*b_j1},  s = 2*log2(e)
// tanh folded into epilogue: o = c - 2*sum(r*v), r = 1/(2^p+1), p clamped <= 31.
__device__ __forceinline__ void feval(float y0, float y1,
                                      const ulonglong2* __restrict__ sW,
                                      const u64* __restrict__ sB,
                                      const ulonglong2* __restrict__ sV,
                                      float c0, float c1,
                                      float& o0, float& o1) {
    const u64 y0p  = pk(y0, y0);
    const u64 y1p  = pk(y1, y1);
    const u64 one2 = 0x3f8000003f800000ull;   // {1.0f, 1.0f}
    u64 a0a = 0ull, a1a = 0ull;
    u64 a0b = 0ull, a1b = 0ull;
#pragma unroll 2
    for (int jp = 0; jp < NH / 2; jp += 2) {
        ulonglong2 W0 = sW[jp];
        ulonglong2 W1 = sW[jp + 1];
        u64 B0 = sB[jp];
        u64 B1 = sB[jp + 1];
        u64 pA = fma2(y0p, W0.x, fma2(y1p, W0.y, B0));  // {p0, p1}
        u64 pB = fma2(y0p, W1.x, fma2(y1p, W1.y, B1));  // {p2, p3}
        float2 a = upk(pA), b = upk(pB);

        float t0 = ex2f(fminf(a.x, 31.0f));
        float t1 = ex2f(fminf(a.y, 31.0f));
        float t2 = ex2f(fminf(b.x, 31.0f));
        float t3 = ex2f(fminf(b.y, 31.0f));

        // Packed 4-way shared reciprocal: one MUFU rcp serves 4 sigmoids.
        // p <= 31 -> u <= 2^31+1, 4-product <= ~2^124 (finite).
        u64 u01 = add2(pk(t0, t1), one2);      // {u0, u1}
        u64 u23 = add2(pk(t2, t3), one2);      // {u2, u3}
        u64 w   = mul2(u01, u23);              // {u0u2, u1u3}
        float2 wf = upk(w);
        float rc  = rcpf(wf.x * wf.y);         // 1/(u0u1u2u3)
        u64 q   = mul2(w, pk(rc, rc));         // {1/(u1u3), 1/(u0u2)}
        float2 qf = upk(q);
        u64 qs  = pk(qf.y, qf.x);              // {1/(u0u2), 1/(u1u3)}
        u64 r01 = mul2(qs, u23);               // {1/u0, 1/u1}
        u64 r23 = mul2(qs, u01);               // {1/u2, 1/u3}

        ulonglong2 V0 = sV[jp];
        ulonglong2 V1 = sV[jp + 1];
        a0a = fma2(r01, V0.x, a0a);
        a1a = fma2(r01, V0.y, a1a);
        a0b = fma2(r23, V1.x, a0b);
        a1b = fma2(r23, V1.y, a1b);
    }
    float2 s0 = upk(add2(a0a, a0b));
    float2 s1 = upk(add2(a1a, a1b));
    o0 = fmaf(-2.0f, s0.x + s0.y, c0);
    o1 = fmaf(-2.0f, s1.x + s1.y, c1);
}

__device__ __forceinline__ void rk_step(float& y0, float& y1,
                                        const ulonglong2* __restrict__ sW,
                                        const u64* __restrict__ sB,
                                        const ulonglong2* __restrict__ sV,
                                        float c0, float c1) {
    const float dt   = (float)(150.0 / 149.0);
    const float dt3  = dt * (1.0f / 3.0f);
    const float dt8  = dt * 0.125f;
    const float thrd = 1.0f / 3.0f;

    float k1x, k1y, k2x, k2y, k3x, k3y, k4x, k4y;
    feval(y0, y1, sW, sB, sV, c0, c1, k1x, k1y);
    feval(fmaf(dt3, k1x, y0), fmaf(dt3, k1y, y1), sW, sB, sV, c0, c1, k2x, k2y);
    feval(fmaf(dt, fmaf(-thrd, k1x, k2x), y0),
          fmaf(dt, fmaf(-thrd, k1y, k2y), y1), sW, sB, sV, c0, c1, k3x, k3y);
    feval(fmaf(dt, (k1x - k2x) + k3x, y0),
          fmaf(dt, (k1y - k2y) + k3y, y1), sW, sB, sV, c0, c1, k4x, k4y);

    y0 = fmaf(dt8, fmaf(3.0f, k2x + k3x, k1x + k4x), y0);
    y1 = fmaf(dt8, fmaf(3.0f, k2y + k3y, k1y + k4y), y1);
}

__global__ void __launch_bounds__(128, 8)
neural_ode_kernel(const float* __restrict__ x,
                  const float* __restrict__ W1,
                  const float* __restrict__ b1,
                  const float* __restrict__ W2,
                  const float* __restrict__ b2,
                  float* __restrict__ out) {
    __shared__ alignas(16) float4 sWf[NH / 2];
    __shared__ alignas(16) float4 sVf[NH / 2];
    __shared__ alignas(8)  float2 sBf[NH / 2];
    __shared__ float sc[2];

    const int tid = threadIdx.x;
    if (tid < NH / 2) {
        const float s = 2.8853900817779268f;  // 2*log2(e)
        int j = 2 * tid;
        sWf[tid] = make_float4(s * W1[j], s * W1[j + 1],
                               s * W1[NH + j], s * W1[NH + j + 1]);
        sBf[tid] = make_float2(s * b1[j], s * b1[j + 1]);
        sVf[tid] = make_float4(W2[2 * j], W2[2 * (j + 1)],
                               W2[2 * j + 1], W2[2 * (j + 1) + 1]);
    }
    if (tid < 2) {
        float c = b2[tid];
        for (int j = 0; j < NH; j++) c += W2[2 * j + tid];
        sc[tid] = c;
    }
    __syncthreads();

    const ulonglong2* sW = reinterpret_cast<const ulonglong2*>(sWf);
    const ulonglong2* sV = reinterpret_cast<const ulonglong2*>(sVf);
    const u64*        sB = reinterpret_cast<const u64*>(sBf);

    const float c0 = sc[0];
    const float c1 = sc[1];

    const long b = (long)blockIdx.x * blockDim.x + tid;

    const float2 yin = *(const float2*)(x + b * (long)(NSEQ * ND) + (NSEQ - 1) * ND);
    float y0 = yin.x;
    float y1 = yin.y;

    float2* ob = (float2*)(out + b * (long)(NPRED * ND));
    ob[0] = make_float2(y0, y1);

#pragma unroll 1
    for (int st = 0; st < NSTEPS; st++) {
        rk_step(y0, y1, sW, sB, sV, c0, c1);
        ob[st + 1] = make_float2(y0, y1);
    }
}

extern "C" void kernel_launch(void* const* d_in, const int* in_sizes, int n_in,
                              void* d_out, int out_size) {
    const float* x  = (const float*)d_in[0];
    const float* W1 = (const float*)d_in[1];
    const float* b1 = (const float*)d_in[2];
    const float* W2 = (const float*)d_in[3];
    const float* b2 = (const float*)d_in[4];
    float* out = (float*)d_out;

    const int block = 128;
    const int grid  = NB / block;  // 1024 CTAs, 4096 warps
    neural_ode_kernel<<<grid, block>>>(x, W1, b1, W2, b2, out);
}

// round 8
// speedup vs baseline: 1.0179x; 1.0179x over previous
#include <cuda_runtime.h>
#include <cuda_bf16.h>

// NeuralODE R8: exact R5 structure (best: 2208us) + bias packing so each
// 4-tanh group does 5 broadcast LDS.128 instead of 4x LDS.128 + 2x LDS.64.
// 1 traj/thread, f32x2 across hidden dim, scalar 4-way shared reciprocal,
// feval unroll 4, 128 thr x 8 CTA (64 regs).

#define NB    131072
#define NSEQ  150
#define ND    2
#define NH    64
#define NPRED 150
#define NSTEPS (NPRED - 1)

typedef unsigned long long u64;

__device__ __forceinline__ u64 pk(float a, float b) {
    u64 r; asm("mov.b64 %0, {%1, %2};" : "=l"(r) : "f"(a), "f"(b)); return r;
}
__device__ __forceinline__ float2 upk(u64 v) {
    float2 r; asm("mov.b64 {%0, %1}, %2;" : "=f"(r.x), "=f"(r.y) : "l"(v)); return r;
}
__device__ __forceinline__ u64 fma2(u64 a, u64 b, u64 c) {
    u64 d; asm("fma.rn.f32x2 %0, %1, %2, %3;" : "=l"(d) : "l"(a), "l"(b), "l"(c)); return d;
}
__device__ __forceinline__ u64 add2(u64 a, u64 b) {
    u64 d; asm("add.rn.f32x2 %0, %1, %2;" : "=l"(d) : "l"(a), "l"(b)); return d;
}
__device__ __forceinline__ float ex2f(float p) {
    float t; asm("ex2.approx.f32 %0, %1;" : "=f"(t) : "f"(p)); return t;
}
__device__ __forceinline__ float rcpf(float p) {
    float t; asm("rcp.approx.f32 %0, %1;" : "=f"(t) : "f"(p)); return t;
}

// Shared layout:
//   sW[jp]  (ulonglong2): { {s*wx_j, s*wx_j1}, {s*wy_j, s*wy_j1} } per hidden pair
//   sV[jp]  (ulonglong2): { {vx_j, vx_j1},     {vy_j, vy_j1} }
//   sB4[g]  (ulonglong2): { {s*b_4g, s*b_4g+1}, {s*b_4g+2, s*b_4g+3} }  per GROUP of 4
//   s = 2*log2(e); tanh folded into epilogue o = c - 2*sum(r*v), r = 1/(2^p+1), p<=31.
__device__ __forceinline__ void feval(float y0, float y1,
                                      const ulonglong2* __restrict__ sW,
                                      const ulonglong2* __restrict__ sB4,
                                      const ulonglong2* __restrict__ sV,
                                      float c0, float c1,
                                      float& o0, float& o1) {
    const u64 y0p = pk(y0, y0);
    const u64 y1p = pk(y1, y1);
    u64 a0a = 0ull, a1a = 0ull;
    u64 a0b = 0ull, a1b = 0ull;
#pragma unroll 4
    for (int jp = 0; jp < NH / 2; jp += 2) {
        ulonglong2 W0 = sW[jp];
        ulonglong2 W1 = sW[jp + 1];
        ulonglong2 Bg = sB4[jp >> 1];          // {b01, b23} one LDS.128
        u64 pA = fma2(y0p, W0.x, fma2(y1p, W0.y, Bg.x));
        u64 pB = fma2(y0p, W1.x, fma2(y1p, W1.y, Bg.y));
        float2 a = upk(pA), b = upk(pB);

        float t0 = ex2f(fminf(a.x, 31.0f));
        float t1 = ex2f(fminf(a.y, 31.0f));
        float t2 = ex2f(fminf(b.x, 31.0f));
        float t3 = ex2f(fminf(b.y, 31.0f));
        float u0 = t0 + 1.0f, u1 = t1 + 1.0f;
        float u2 = t2 + 1.0f, u3 = t3 + 1.0f;

        // 4-way shared reciprocal: one MUFU rcp serves 4 sigmoids.
        // p <= 31 -> u <= 2^31+1, 4-product <= ~2^124 (finite).
        float m01 = u0 * u1;
        float m23 = u2 * u3;
        float rc  = rcpf(m01 * m23);
        float rA  = rc * m23;                  // = 1/m01
        float rB  = rc * m01;                  // = 1/m23
        u64 r01 = pk(rA * u1, rA * u0);        // {1/u0, 1/u1}
        u64 r23 = pk(rB * u3, rB * u2);        // {1/u2, 1/u3}

        ulonglong2 V0 = sV[jp];
        ulonglong2 V1 = sV[jp + 1];
        a0a = fma2(r01, V0.x, a0a);
        a1a = fma2(r01, V0.y, a1a);
        a0b = fma2(r23, V1.x, a0b);
        a1b = fma2(r23, V1.y, a1b);
    }
    float2 s0 = upk(add2(a0a, a0b));
    float2 s1 = upk(add2(a1a, a1b));
    o0 = fmaf(-2.0f, s0.x + s0.y, c0);
    o1 = fmaf(-2.0f, s1.x + s1.y, c1);
}

__global__ void __launch_bounds__(128, 8)
neural_ode_kernel(const float* __restrict__ x,
                  const float* __restrict__ W1,
                  const float* __restrict__ b1,
                  const float* __restrict__ W2,
                  const float* __restrict__ b2,
                  float* __restrict__ out) {
    __shared__ alignas(16) float4 sWf[NH / 2];
    __shared__ alignas(16) float4 sVf[NH / 2];
    __shared__ alignas(16) float4 sBf[NH / 4];
    __shared__ float sc[2];

    const int tid = threadIdx.x;
    if (tid < NH / 2) {
        const float s = 2.8853900817779268f;  // 2*log2(e)
        int j = 2 * tid;
        sWf[tid] = make_float4(s * W1[j], s * W1[j + 1],
                               s * W1[NH + j], s * W1[NH + j + 1]);
        sVf[tid] = make_float4(W2[2 * j], W2[2 * (j + 1)],
                               W2[2 * j + 1], W2[2 * (j + 1) + 1]);
    }
    if (tid < NH / 4) {
        const float s = 2.8853900817779268f;
        int j = 4 * tid;
        sBf[tid] = make_float4(s * b1[j], s * b1[j + 1],
                               s * b1[j + 2], s * b1[j + 3]);
    }
    if (tid < 2) {
        float c = b2[tid];
        for (int j = 0; j < NH; j++) c += W2[2 * j + tid];
        sc[tid] = c;
    }
    __syncthreads();

    const ulonglong2* sW  = reinterpret_cast<const ulonglong2*>(sWf);
    const ulonglong2* sV  = reinterpret_cast<const ulonglong2*>(sVf);
    const ulonglong2* sB4 = reinterpret_cast<const ulonglong2*>(sBf);

    const float c0 = sc[0];
    const float c1 = sc[1];

    const long b = (long)blockIdx.x * blockDim.x + tid;

    const float2 yin = *(const float2*)(x + b * (long)(NSEQ * ND) + (NSEQ - 1) * ND);
    float y0 = yin.x;
    float y1 = yin.y;

    float2* ob = (float2*)(out + b * (long)(NPRED * ND));
    ob[0] = make_float2(y0, y1);

    const float dt   = (float)(150.0 / 149.0);
    const float dt3  = dt * (1.0f / 3.0f);
    const float dt8  = dt * 0.125f;
    const float thrd = 1.0f / 3.0f;

#pragma unroll 1
    for (int st = 0; st < NSTEPS; st++) {
        float k1x, k1y, k2x, k2y, k3x, k3y, k4x, k4y;

        feval(y0, y1, sW, sB4, sV, c0, c1, k1x, k1y);
        feval(fmaf(dt3, k1x, y0), fmaf(dt3, k1y, y1),
              sW, sB4, sV, c0, c1, k2x, k2y);
        feval(fmaf(dt, fmaf(-thrd, k1x, k2x), y0),
              fmaf(dt, fmaf(-thrd, k1y, k2y), y1),
              sW, sB4, sV, c0, c1, k3x, k3y);
        feval(fmaf(dt, (k1x - k2x) + k3x, y0),
              fmaf(dt, (k1y - k2y) + k3y, y1),
              sW, sB4, sV, c0, c1, k4x, k4y);

        y0 = fmaf(dt8, fmaf(3.0f, k2x + k3x, k1x + k4x), y0);
        y1 = fmaf(dt8, fmaf(3.0f, k2y + k3y, k1y + k4y), y1);

        ob[st + 1] = make_float2(y0, y1);
    }
}

extern "C" void kernel_launch(void* const* d_in, const int* in_sizes, int n_in,
                              void* d_out, int out_size) {
    const float* x  = (const float*)d_in[0];
    const float* W1 = (const float*)d_in[1];
    const float* b1 = (const float*)d_in[2];
    const float* W2 = (const float*)d_in[3];
    const float* b2 = (const float*)d_in[4];
    float* out = (float*)d_out;

    const int block = 128;
    const int grid  = NB / block;  // 1024 CTAs, 4096 warps
    neural_ode_kernel<<<grid, block>>>(x, W1, b1, W2, b2, out);
}

// round 9
// speedup vs baseline: 1.0320x; 1.0139x over previous
#include <cuda_runtime.h>
#include <cuda_bf16.h>

// NeuralODE R9: R8 + packed-u fixup. u-vectors built in swapped lane order
// ({u1,u0}) so r01 = splat(rA) * u10 lands in natural lane order with no
// lane swap and no extra unpack. Scalar m-chain, unroll 4, 128thr x 8 CTA
// all preserved from the validated R5/R8 structure.

#define NB    131072
#define NSEQ  150
#define ND    2
#define NH    64
#define NPRED 150
#define NSTEPS (NPRED - 1)

typedef unsigned long long u64;

__device__ __forceinline__ u64 pk(float a, float b) {
    u64 r; asm("mov.b64 %0, {%1, %2};" : "=l"(r) : "f"(a), "f"(b)); return r;
}
__device__ __forceinline__ float2 upk(u64 v) {
    float2 r; asm("mov.b64 {%0, %1}, %2;" : "=f"(r.x), "=f"(r.y) : "l"(v)); return r;
}
__device__ __forceinline__ u64 fma2(u64 a, u64 b, u64 c) {
    u64 d; asm("fma.rn.f32x2 %0, %1, %2, %3;" : "=l"(d) : "l"(a), "l"(b), "l"(c)); return d;
}
__device__ __forceinline__ u64 add2(u64 a, u64 b) {
    u64 d; asm("add.rn.f32x2 %0, %1, %2;" : "=l"(d) : "l"(a), "l"(b)); return d;
}
__device__ __forceinline__ u64 mul2(u64 a, u64 b) {
    u64 d; asm("mul.rn.f32x2 %0, %1, %2;" : "=l"(d) : "l"(a), "l"(b)); return d;
}
__device__ __forceinline__ float ex2f(float p) {
    float t; asm("ex2.approx.f32 %0, %1;" : "=f"(t) : "f"(p)); return t;
}
__device__ __forceinline__ float rcpf(float p) {
    float t; asm("rcp.approx.f32 %0, %1;" : "=f"(t) : "f"(p)); return t;
}

// Shared layout:
//   sW[jp]  (ulonglong2): { {s*wx_j, s*wx_j1}, {s*wy_j, s*wy_j1} } per hidden pair
//   sV[jp]  (ulonglong2): { {vx_j, vx_j1},     {vy_j, vy_j1} }
//   sB4[g]  (ulonglong2): { {s*b_4g, s*b_4g+1}, {s*b_4g+2, s*b_4g+3} }
//   s = 2*log2(e); tanh folded into epilogue o = c - 2*sum(r*v), r = 1/(2^p+1), p<=31.
__device__ __forceinline__ void feval(float y0, float y1,
                                      const ulonglong2* __restrict__ sW,
                                      const ulonglong2* __restrict__ sB4,
                                      const ulonglong2* __restrict__ sV,
                                      float c0, float c1,
                                      float& o0, float& o1) {
    const u64 y0p  = pk(y0, y0);
    const u64 y1p  = pk(y1, y1);
    const u64 one2 = 0x3f8000003f800000ull;   // {1.0f, 1.0f}
    u64 a0a = 0ull, a1a = 0ull;
    u64 a0b = 0ull, a1b = 0ull;
#pragma unroll 4
    for (int jp = 0; jp < NH / 2; jp += 2) {
        ulonglong2 W0 = sW[jp];
        ulonglong2 W1 = sW[jp + 1];
        ulonglong2 Bg = sB4[jp >> 1];
        u64 pA = fma2(y0p, W0.x, fma2(y1p, W0.y, Bg.x));  // {p0, p1} = units {j, j+1}
        u64 pB = fma2(y0p, W1.x, fma2(y1p, W1.y, Bg.y));  // {p2, p3}
        float2 a = upk(pA), b = upk(pB);

        float t0 = ex2f(fminf(a.x, 31.0f));
        float t1 = ex2f(fminf(a.y, 31.0f));
        float t2 = ex2f(fminf(b.x, 31.0f));
        float t3 = ex2f(fminf(b.y, 31.0f));

        // Packed u in SWAPPED lane order: u10 = {u1, u0}, u32 = {u3, u2}.
        u64 u10 = add2(pk(t1, t0), one2);
        u64 u32 = add2(pk(t3, t2), one2);
        float2 ua = upk(u10);                  // .x = u1, .y = u0 (register halves)
        float2 ub = upk(u32);                  // .x = u3, .y = u2

        // 4-way shared reciprocal (one MUFU rcp per 4 sigmoids).
        // p <= 31 -> u <= 2^31+1, 4-product <= ~2^124 (finite).
        float m01 = ua.x * ua.y;               // u0*u1
        float m23 = ub.x * ub.y;               // u2*u3
        float rc  = rcpf(m01 * m23);
        float rA  = rc * m23;                  // 1/(u0*u1)
        float rB  = rc * m01;                  // 1/(u2*u3)

        // Swapped-u trick: splat(rA) * {u1,u0} = {1/u0, 1/u1} in natural order.
        u64 r01 = mul2(pk(rA, rA), u10);
        u64 r23 = mul2(pk(rB, rB), u32);

        ulonglong2 V0 = sV[jp];
        ulonglong2 V1 = sV[jp + 1];
        a0a = fma2(r01, V0.x, a0a);
        a1a = fma2(r01, V0.y, a1a);
        a0b = fma2(r23, V1.x, a0b);
        a1b = fma2(r23, V1.y, a1b);
    }
    float2 s0 = upk(add2(a0a, a0b));
    float2 s1 = upk(add2(a1a, a1b));
    o0 = fmaf(-2.0f, s0.x + s0.y, c0);
    o1 = fmaf(-2.0f, s1.x + s1.y, c1);
}

__global__ void __launch_bounds__(128, 8)
neural_ode_kernel(const float* __restrict__ x,
                  const float* __restrict__ W1,
                  const float* __restrict__ b1,
                  const float* __restrict__ W2,
                  const float* __restrict__ b2,
                  float* __restrict__ out) {
    __shared__ alignas(16) float4 sWf[NH / 2];
    __shared__ alignas(16) float4 sVf[NH / 2];
    __shared__ alignas(16) float4 sBf[NH / 4];
    __shared__ float sc[2];

    const int tid = threadIdx.x;
    if (tid < NH / 2) {
        const float s = 2.8853900817779268f;  // 2*log2(e)
        int j = 2 * tid;
        sWf[tid] = make_float4(s * W1[j], s * W1[j + 1],
                               s * W1[NH + j], s * W1[NH + j + 1]);
        sVf[tid] = make_float4(W2[2 * j], W2[2 * (j + 1)],
                               W2[2 * j + 1], W2[2 * (j + 1) + 1]);
    }
    if (tid < NH / 4) {
        const float s = 2.8853900817779268f;
        int j = 4 * tid;
        sBf[tid] = make_float4(s * b1[j], s * b1[j + 1],
                               s * b1[j + 2], s * b1[j + 3]);
    }
    if (tid < 2) {
        float c = b2[tid];
        for (int j = 0; j < NH; j++) c += W2[2 * j + tid];
        sc[tid] = c;
    }
    __syncthreads();

    const ulonglong2* sW  = reinterpret_cast<const ulonglong2*>(sWf);
    const ulonglong2* sV  = reinterpret_cast<const ulonglong2*>(sVf);
    const ulonglong2* sB4 = reinterpret_cast<const ulonglong2*>(sBf);

    const float c0 = sc[0];
    const float c1 = sc[1];

    const long b = (long)blockIdx.x * blockDim.x + tid;

    const float2 yin = *(const float2*)(x + b * (long)(NSEQ * ND) + (NSEQ - 1) * ND);
    float y0 = yin.x;
    float y1 = yin.y;

    float2* ob = (float2*)(out + b * (long)(NPRED * ND));
    ob[0] = make_float2(y0, y1);

    const float dt   = (float)(150.0 / 149.0);
    const float dt3  = dt * (1.0f / 3.0f);
    const float dt8  = dt * 0.125f;
    const float thrd = 1.0f / 3.0f;

#pragma unroll 1
    for (int st = 0; st < NSTEPS; st++) {
        float k1x, k1y, k2x, k2y, k3x, k3y, k4x, k4y;

        feval(y0, y1, sW, sB4, sV, c0, c1, k1x, k1y);
        feval(fmaf(dt3, k1x, y0), fmaf(dt3, k1y, y1),
              sW, sB4, sV, c0, c1, k2x, k2y);
        feval(fmaf(dt, fmaf(-thrd, k1x, k2x), y0),
              fmaf(dt, fmaf(-thrd, k1y, k2y), y1),
              sW, sB4, sV, c0, c1, k3x, k3y);
        feval(fmaf(dt, (k1x - k2x) + k3x, y0),
              fmaf(dt, (k1y - k2y) + k3y, y1),
              sW, sB4, sV, c0, c1, k4x, k4y);

        y0 = fmaf(dt8, fmaf(3.0f, k2x + k3x, k1x + k4x), y0);
        y1 = fmaf(dt8, fmaf(3.0f, k2y + k3y, k1y + k4y), y1);

        ob[st + 1] = make_float2(y0, y1);
    }
}

extern "C" void kernel_launch(void* const* d_in, const int* in_sizes, int n_in,
                              void* d_out, int out_size) {
    const float* x  = (const float*)d_in[0];
    const float* W1 = (const float*)d_in[1];
    const float* b1 = (const float*)d_in[2];
    const float* W2 = (const float*)d_in[3];
    const float* b2 = (const float*)d_in[4];
    float* out = (float*)d_out;

    const int block = 128;
    const int grid  = NB / block;  // 1024 CTAs, 4096 warps
    neural_ode_kernel<<<grid, block>>>(x, W1, b1, W2, b2, out);
}

// round 10
// speedup vs baseline: 1.0620x; 1.0291x over previous
#include <cuda_runtime.h>
#include <cuda_bf16.h>

// NeuralODE R10: identical math to R9 (best: 2174us). Two scheduling changes:
//  - __launch_bounds__(128, 7): occupancy is grid-limited (6.92 CTAs/SM), so
//    relaxing the reg cap 64 -> 73 costs no warps and frees ptxas.
//  - feval unroll 8: 8 independent ex2 + 2 independent rcp chains per trip,
//    deeper MUFU ILP to close the 77% -> ~85% issue-efficiency gap.

#define NB    131072
#define NSEQ  150
#define ND    2
#define NH    64
#define NPRED 150
#define NSTEPS (NPRED - 1)

typedef unsigned long long u64;

__device__ __forceinline__ u64 pk(float a, float b) {
    u64 r; asm("mov.b64 %0, {%1, %2};" : "=l"(r) : "f"(a), "f"(b)); return r;
}
__device__ __forceinline__ float2 upk(u64 v) {
    float2 r; asm("mov.b64 {%0, %1}, %2;" : "=f"(r.x), "=f"(r.y) : "l"(v)); return r;
}
__device__ __forceinline__ u64 fma2(u64 a, u64 b, u64 c) {
    u64 d; asm("fma.rn.f32x2 %0, %1, %2, %3;" : "=l"(d) : "l"(a), "l"(b), "l"(c)); return d;
}
__device__ __forceinline__ u64 add2(u64 a, u64 b) {
    u64 d; asm("add.rn.f32x2 %0, %1, %2;" : "=l"(d) : "l"(a), "l"(b)); return d;
}
__device__ __forceinline__ u64 mul2(u64 a, u64 b) {
    u64 d; asm("mul.rn.f32x2 %0, %1, %2;" : "=l"(d) : "l"(a), "l"(b)); return d;
}
__device__ __forceinline__ float ex2f(float p) {
    float t; asm("ex2.approx.f32 %0, %1;" : "=f"(t) : "f"(p)); return t;
}
__device__ __forceinline__ float rcpf(float p) {
    float t; asm("rcp.approx.f32 %0, %1;" : "=f"(t) : "f"(p)); return t;
}

// Shared layout:
//   sW[jp]  (ulonglong2): { {s*wx_j, s*wx_j1}, {s*wy_j, s*wy_j1} } per hidden pair
//   sV[jp]  (ulonglong2): { {vx_j, vx_j1},     {vy_j, vy_j1} }
//   sB4[g]  (ulonglong2): { {s*b_4g, s*b_4g+1}, {s*b_4g+2, s*b_4g+3} }
//   s = 2*log2(e); tanh folded into epilogue o = c - 2*sum(r*v), r = 1/(2^p+1), p<=31.
__device__ __forceinline__ void feval(float y0, float y1,
                                      const ulonglong2* __restrict__ sW,
                                      const ulonglong2* __restrict__ sB4,
                                      const ulonglong2* __restrict__ sV,
                                      float c0, float c1,
                                      float& o0, float& o1) {
    const u64 y0p  = pk(y0, y0);
    const u64 y1p  = pk(y1, y1);
    const u64 one2 = 0x3f8000003f800000ull;   // {1.0f, 1.0f}
    u64 a0a = 0ull, a1a = 0ull;
    u64 a0b = 0ull, a1b = 0ull;
#pragma unroll 8
    for (int jp = 0; jp < NH / 2; jp += 2) {
        ulonglong2 W0 = sW[jp];
        ulonglong2 W1 = sW[jp + 1];
        ulonglong2 Bg = sB4[jp >> 1];
        u64 pA = fma2(y0p, W0.x, fma2(y1p, W0.y, Bg.x));  // {p0, p1} = units {j, j+1}
        u64 pB = fma2(y0p, W1.x, fma2(y1p, W1.y, Bg.y));  // {p2, p3}
        float2 a = upk(pA), b = upk(pB);

        float t0 = ex2f(fminf(a.x, 31.0f));
        float t1 = ex2f(fminf(a.y, 31.0f));
        float t2 = ex2f(fminf(b.x, 31.0f));
        float t3 = ex2f(fminf(b.y, 31.0f));

        // Packed u in SWAPPED lane order: u10 = {u1, u0}, u32 = {u3, u2}.
        u64 u10 = add2(pk(t1, t0), one2);
        u64 u32 = add2(pk(t3, t2), one2);
        float2 ua = upk(u10);                  // .x = u1, .y = u0
        float2 ub = upk(u32);                  // .x = u3, .y = u2

        // 4-way shared reciprocal (one MUFU rcp per 4 sigmoids).
        // p <= 31 -> u <= 2^31+1, 4-product <= ~2^124 (finite).
        float m01 = ua.x * ua.y;               // u0*u1
        float m23 = ub.x * ub.y;               // u2*u3
        float rc  = rcpf(m01 * m23);
        float rA  = rc * m23;                  // 1/(u0*u1)
        float rB  = rc * m01;                  // 1/(u2*u3)

        // Swapped-u trick: splat(rA) * {u1,u0} = {1/u0, 1/u1} in natural order.
        u64 r01 = mul2(pk(rA, rA), u10);
        u64 r23 = mul2(pk(rB, rB), u32);

        ulonglong2 V0 = sV[jp];
        ulonglong2 V1 = sV[jp + 1];
        a0a = fma2(r01, V0.x, a0a);
        a1a = fma2(r01, V0.y, a1a);
        a0b = fma2(r23, V1.x, a0b);
        a1b = fma2(r23, V1.y, a1b);
    }
    float2 s0 = upk(add2(a0a, a0b));
    float2 s1 = upk(add2(a1a, a1b));
    o0 = fmaf(-2.0f, s0.x + s0.y, c0);
    o1 = fmaf(-2.0f, s1.x + s1.y, c1);
}

__global__ void __launch_bounds__(128, 7)
neural_ode_kernel(const float* __restrict__ x,
                  const float* __restrict__ W1,
                  const float* __restrict__ b1,
                  const float* __restrict__ W2,
                  const float* __restrict__ b2,
                  float* __restrict__ out) {
    __shared__ alignas(16) float4 sWf[NH / 2];
    __shared__ alignas(16) float4 sVf[NH / 2];
    __shared__ alignas(16) float4 sBf[NH / 4];
    __shared__ float sc[2];

    const int tid = threadIdx.x;
    if (tid < NH / 2) {
        const float s = 2.8853900817779268f;  // 2*log2(e)
        int j = 2 * tid;
        sWf[tid] = make_float4(s * W1[j], s * W1[j + 1],
                               s * W1[NH + j], s * W1[NH + j + 1]);
        sVf[tid] = make_float4(W2[2 * j], W2[2 * (j + 1)],
                               W2[2 * j + 1], W2[2 * (j + 1) + 1]);
    }
    if (tid < NH / 4) {
        const float s = 2.8853900817779268f;
        int j = 4 * tid;
        sBf[tid] = make_float4(s * b1[j], s * b1[j + 1],
                               s * b1[j + 2], s * b1[j + 3]);
    }
    if (tid < 2) {
        float c = b2[tid];
        for (int j = 0; j < NH; j++) c += W2[2 * j + tid];
        sc[tid] = c;
    }
    __syncthreads();

    const ulonglong2* sW  = reinterpret_cast<const ulonglong2*>(sWf);
    const ulonglong2* sV  = reinterpret_cast<const ulonglong2*>(sVf);
    const ulonglong2* sB4 = reinterpret_cast<const ulonglong2*>(sBf);

    const float c0 = sc[0];
    const float c1 = sc[1];

    const long b = (long)blockIdx.x * blockDim.x + tid;

    const float2 yin = *(const float2*)(x + b * (long)(NSEQ * ND) + (NSEQ - 1) * ND);
    float y0 = yin.x;
    float y1 = yin.y;

    float2* ob = (float2*)(out + b * (long)(NPRED * ND));
    ob[0] = make_float2(y0, y1);

    const float dt   = (float)(150.0 / 149.0);
    const float dt3  = dt * (1.0f / 3.0f);
    const float dt8  = dt * 0.125f;
    const float thrd = 1.0f / 3.0f;

#pragma unroll 1
    for (int st = 0; st < NSTEPS; st++) {
        float k1x, k1y, k2x, k2y, k3x, k3y, k4x, k4y;

        feval(y0, y1, sW, sB4, sV, c0, c1, k1x, k1y);
        feval(fmaf(dt3, k1x, y0), fmaf(dt3, k1y, y1),
              sW, sB4, sV, c0, c1, k2x, k2y);
        feval(fmaf(dt, fmaf(-thrd, k1x, k2x), y0),
              fmaf(dt, fmaf(-thrd, k1y, k2y), y1),
              sW, sB4, sV, c0, c1, k3x, k3y);
        feval(fmaf(dt, (k1x - k2x) + k3x, y0),
              fmaf(dt, (k1y - k2y) + k3y, y1),
              sW, sB4, sV, c0, c1, k4x, k4y);

        y0 = fmaf(dt8, fmaf(3.0f, k2x + k3x, k1x + k4x), y0);
        y1 = fmaf(dt8, fmaf(3.0f, k2y + k3y, k1y + k4y), y1);

        ob[st + 1] = make_float2(y0, y1);
    }
}

extern "C" void kernel_launch(void* const* d_in, const int* in_sizes, int n_in,
                              void* d_out, int out_size) {
    const float* x  = (const float*)d_in[0];
    const float* W1 = (const float*)d_in[1];
    const float* b1 = (const float*)d_in[2];
    const float* W2 = (const float*)d_in[3];
    const float* b2 = (const float*)d_in[4];
    float* out = (float*)d_out;

    const int block = 128;
    const int grid  = NB / block;  // 1024 CTAs, 4096 warps
    neural_ode_kernel<<<grid, block>>>(x, W1, b1, W2, b2, out);
}